// round 17
// baseline (speedup 1.0000x reference)
#include <cuda_runtime.h>
#include <cuda_fp16.h>
#include <cuda_bf16.h>
#include <cstdint>

// GAT N=2048, IN=1024, H=8, F=32, slope=0.2 — fused HMMA pipeline (4 kernels).
//  K1 prep:        h,W -> gmem-resident fp16 mma fragment layout (afrag uint4,
//                  wfrag uint2) — removes all in-loop smem shuffling from K2.
//  K2 hgemm_fused: g = h @ W via direct frag LDG + HMMA (no smem mainloop),
//                  interleaved adj->bitmask; epilogue computes fp16 scores
//                  (u1,u2,e1,e2,thr) and writes g as attn B-fragments
//                  (40 N-rows: f0..31=g, f32=ones->Z, pad 0).
//  K3 attn:        half2 W-gen in A-fragment registers (no exp), mma.sync,
//                  128-row i-tiles, NSPLIT=4 j-splits
//  K4 norm:        out = sum(num)/sum(Z), 4 floats/thread, 512 CTAs

#define N_NODES 2048
#define IN_F    1024
#define NH      8
#define NF      32
#define GDIM    256
#define NSPLIT  4
#define JSPAN   (N_NODES/NSPLIT)   // 512
#define NKG     (IN_F/16)          // 64 k-groups
#define NMFG    (N_NODES/16)       // 128 m-frag rows
#define NNFG    (GDIM/8)           // 32 n-frag cols

__device__ __half g_u1h[NH * N_NODES];
__device__ __half g_u2h[NH * N_NODES];
__device__ __half g_e1h[NH * N_NODES];
__device__ __half g_e2h[NH * N_NODES];
__device__ __half g_thrh[NH * N_NODES];
__device__ uint2  g_bfragHI[NH * 128 * 5 * 32];
__device__ uint32_t g_adjbits[N_NODES * (N_NODES / 32)];
__device__ float  g_pnum[NSPLIT][N_NODES * GDIM];
__device__ float  g_pz[NSPLIT][N_NODES * NH];
__device__ uint4  g_afrag[NKG * NMFG * 32];   // 4 MB
__device__ uint2  g_wfrag[NKG * NNFG * 32];   // 512 KB

__device__ __forceinline__ uint32_t h2u(__half2 v) { return *(uint32_t*)&v; }
__device__ __forceinline__ __half2 u2h2(uint32_t v) { return *(__half2*)&v; }

__device__ __forceinline__ void mma16816(float* c, const uint32_t* a, const uint2 b) {
    asm volatile(
        "mma.sync.aligned.m16n8k16.row.col.f32.f16.f16.f32 "
        "{%0,%1,%2,%3}, {%4,%5,%6,%7}, {%8,%9}, {%0,%1,%2,%3};"
        : "+f"(c[0]), "+f"(c[1]), "+f"(c[2]), "+f"(c[3])
        : "r"(a[0]), "r"(a[1]), "r"(a[2]), "r"(a[3]), "r"(b.x), "r"(b.y));
}

// ---------------- K1: prep h,W -> fragment layouts ----------------
// blocks 0..1023: A frags (64 kg x 128 mfg x 32 ln). blocks 1024..1279: W frags.
__global__ __launch_bounds__(256) void prep_kernel(const float* __restrict__ A,
                                                   const float* __restrict__ W) {
    const int t = blockIdx.x * 256 + threadIdx.x;
    if (blockIdx.x < 1024) {
        const int ln = t & 31;
        const int fl = t >> 5;
        const int mfg = fl & (NMFG - 1);
        const int kg  = fl >> 7;
        const int r0 = mfg * 16 + (ln >> 2);
        const int c0 = kg * 16 + (ln & 3) * 2;
        float2 x00 = *(const float2*)&A[r0 * IN_F + c0];
        float2 x10 = *(const float2*)&A[(r0 + 8) * IN_F + c0];
        float2 x01 = *(const float2*)&A[r0 * IN_F + c0 + 8];
        float2 x11 = *(const float2*)&A[(r0 + 8) * IN_F + c0 + 8];
        g_afrag[t] = make_uint4(
            h2u(__floats2half2_rn(x00.x, x00.y)),
            h2u(__floats2half2_rn(x10.x, x10.y)),
            h2u(__floats2half2_rn(x01.x, x01.y)),
            h2u(__floats2half2_rn(x11.x, x11.y)));
    } else {
        const int t2 = t - 1024 * 256;          // < 65536
        const int ln = t2 & 31;
        const int fl = t2 >> 5;
        const int nfg = fl & (NNFG - 1);
        const int kg  = fl >> 5;
        const int n = nfg * 8 + (ln >> 2);
        const int k = kg * 16 + (ln & 3) * 2;
        float b0 = W[k * GDIM + n];
        float b1 = W[(k + 1) * GDIM + n];
        float b2 = W[(k + 8) * GDIM + n];
        float b3 = W[(k + 9) * GDIM + n];
        g_wfrag[t2] = make_uint2(h2u(__floats2half2_rn(b0, b1)),
                                 h2u(__floats2half2_rn(b2, b3)));
    }
}

// ---------------- K2: g = h@W via direct frag LDG + adjbits + score + bfrag ----------------
#define TSTRIDE 68
__global__ __launch_bounds__(256) void hgemm_fused(const float* __restrict__ av,
                                                   const int* __restrict__ adj) {
    __shared__ float tile[64][TSTRIDE]; // 17.4 KB
    __shared__ float as[2 * NF];

    const int tid = threadIdx.x, wid = tid >> 5, lane = tid & 31;
    const int bm = blockIdx.y << 6, bn = blockIdx.x << 6;
    const int wm = wid & 1, wn = wid >> 1;

    if (tid < 2 * NF) as[tid] = av[tid];

    // adjbits slice: CTA handles 1024 words, warp 128, 2 per k-iter
    const int cta = blockIdx.y * 4 + blockIdx.x;     // gridDim.x == 4
    const long wbase = (long)cta * 1024 + wid * 128;

    const int mf0 = (bm >> 4) + wm * 2;              // m-frag base for this warp
    const int nf0 = (bn >> 3) + wn * 2;              // n-frag base for this warp

    float acc[2][2][4];
#pragma unroll
    for (int mf = 0; mf < 2; mf++)
#pragma unroll
        for (int nf = 0; nf < 2; nf++)
#pragma unroll
            for (int q = 0; q < 4; q++) acc[mf][nf][q] = 0.f;

#pragma unroll 2
    for (int kg = 0; kg < NKG; kg++) {
        uint4 a0 = g_afrag[(kg * NMFG + mf0) * 32 + lane];
        uint4 a1 = g_afrag[(kg * NMFG + mf0 + 1) * 32 + lane];
        uint2 b0 = g_wfrag[(kg * NNFG + nf0) * 32 + lane];
        uint2 b1 = g_wfrag[(kg * NNFG + nf0 + 1) * 32 + lane];
        // adj loads (consumed after MMAs)
        const long w0 = wbase + kg * 2;
        int v0 = adj[w0 * 32 + lane];
        int v1 = adj[w0 * 32 + 32 + lane];

        uint32_t ah0[4] = {a0.x, a0.y, a0.z, a0.w};
        uint32_t ah1[4] = {a1.x, a1.y, a1.z, a1.w};
        mma16816(acc[0][0], ah0, b0);
        mma16816(acc[0][1], ah0, b1);
        mma16816(acc[1][0], ah1, b0);
        mma16816(acc[1][1], ah1, b1);

        uint32_t m0 = __ballot_sync(0xFFFFFFFFu, v0 != 0);
        uint32_t m1 = __ballot_sync(0xFFFFFFFFu, v1 != 0);
        if (lane < 2) g_adjbits[w0 + lane] = lane ? m1 : m0;
    }

    // ---- epilogue: stage tile, then score + bfrag ----
    const int rq = lane >> 2, cq = (lane & 3) * 2;
#pragma unroll
    for (int mf = 0; mf < 2; mf++) {
        int r0 = (wm * 2 + mf) * 16 + rq;
#pragma unroll
        for (int nf = 0; nf < 2; nf++) {
            int col = (wn * 2 + nf) * 8 + cq;
            tile[r0][col]     = acc[mf][nf][0];
            tile[r0][col + 1] = acc[mf][nf][1];
            tile[r0 + 8][col]     = acc[mf][nf][2];
            tile[r0 + 8][col + 1] = acc[mf][nf][3];
        }
    }
    __syncthreads();

    if (tid < 128) {   // score: 64 rows x 2 heads
        int row = tid & 63, hh = tid >> 6;
        int node = bm + row;
        int head = (bn >> 5) + hh;
        const float* tp = &tile[row][hh * 32];
        float sl = 0.f, sr = 0.f;
#pragma unroll
        for (int c = 0; c < 8; c++) {
            float4 v = *(const float4*)&tp[c * 4];
            sl = fmaf(v.x, as[c*4+0], sl); sl = fmaf(v.y, as[c*4+1], sl);
            sl = fmaf(v.z, as[c*4+2], sl); sl = fmaf(v.w, as[c*4+3], sl);
            sr = fmaf(v.x, as[NF+c*4+0], sr); sr = fmaf(v.y, as[NF+c*4+1], sr);
            sr = fmaf(v.z, as[NF+c*4+2], sr); sr = fmaf(v.w, as[NF+c*4+3], sr);
        }
        const int o = head * N_NODES + node;
        g_u1h[o]  = __float2half_rn(expf(sr));
        g_u2h[o]  = __float2half_rn(expf(0.2f * sr));
        g_e1h[o]  = __float2half_rn(expf(sl));
        g_e2h[o]  = __float2half_rn(expf(0.2f * sl));
        g_thrh[o] = __float2half_rn(expf(-sl));
    }

    // bfrag: 40 fragments per CTA, 8 warps x 5
    const int n = lane >> 2, kq = (lane & 3) * 2;
#pragma unroll
    for (int t = 0; t < 5; t++) {
        int fid = wid * 5 + t;
        uint2 frag;
        int hh, jgl, nfr;
        if (fid < 32) {
            hh = fid >> 4; jgl = (fid >> 2) & 3; nfr = fid & 3;
            int f = nfr * 8 + n;
            float v[4];
#pragma unroll
            for (int r = 0; r < 2; r++)
#pragma unroll
                for (int s = 0; s < 2; s++)
                    v[r * 2 + s] = tile[jgl * 16 + r * 8 + kq + s][hh * 32 + f];
            frag = make_uint2(
                h2u(__halves2half2(__float2half_rn(v[0]), __float2half_rn(v[1]))),
                h2u(__halves2half2(__float2half_rn(v[2]), __float2half_rn(v[3]))));
        } else {
            int p = fid - 32;
            hh = p >> 2; jgl = p & 3; nfr = 4;
            uint32_t ones = (n == 0) ? 0x3C003C00u : 0u;
            frag = make_uint2(ones, ones);
        }
        int head = (bn >> 5) + hh;
        int jg = (bm >> 4) + jgl;
        g_bfragHI[((long)(head * 128 + jg) * 5 + nfr) * 32 + lane] = frag;
    }
}

// ---------------- K3: HMMA attention aggregation (128-row tiles, half2 W-gen) ----------------
__global__ __launch_bounds__(256, 1) void attn_kernel() {
    __shared__ uint32_t adjw[2][128];
    __shared__ __half u1s[2][128];   // [4 h][32 j]
    __shared__ __half u2s[2][128];

    const int tid = threadIdx.x, wid = tid >> 5, lane = tid & 31;
    const int i0 = blockIdx.x * 128;
    const int hg = blockIdx.y;
    const int sp = blockIdx.z;
    const int j00 = sp * JSPAN;

    const int hloc  = wid >> 1;
    const int hglob = hg * 4 + hloc;
    const int ihalf = (wid & 1) * 64;
    const int rq = lane >> 2;
    const int kq = (lane & 3) * 2;

    __half2 th2[4][2], e2b[4][2], ed[4][2];
#pragma unroll
    for (int mf = 0; mf < 4; mf++)
#pragma unroll
        for (int rs = 0; rs < 2; rs++) {
            int r = i0 + ihalf + mf * 16 + rq + rs * 8;
            __half e1 = g_e1h[hglob * N_NODES + r];
            __half e2 = g_e2h[hglob * N_NODES + r];
            th2[mf][rs] = __half2half2(g_thrh[hglob * N_NODES + r]);
            e2b[mf][rs] = __half2half2(e2);
            ed[mf][rs]  = __half2half2(__hsub(e1, e2));
        }

    float acc[4][5][4];
#pragma unroll
    for (int mf = 0; mf < 4; mf++)
#pragma unroll
        for (int nf = 0; nf < 5; nf++)
#pragma unroll
            for (int q = 0; q < 4; q++) acc[mf][nf][q] = 0.f;

    {   // stage chunk 0
        const int j0c = j00;
        if (tid < 128) {
            adjw[0][tid] = g_adjbits[(i0 + tid) * (N_NODES / 32) + (j0c >> 5)];
            u1s[0][tid] = g_u1h[(hg * 4 + (tid >> 5)) * N_NODES + j0c + (tid & 31)];
        } else {
            int q = tid - 128;
            u2s[0][q] = g_u2h[(hg * 4 + (q >> 5)) * N_NODES + j0c + (q & 31)];
        }
    }
    __syncthreads();

    for (int c = 0; c < 16; c++) {
        const int j0c = j00 + c * 32;
        const int buf = c & 1;
        uint2 bh[2][5];
#pragma unroll
        for (int ks = 0; ks < 2; ks++) {
            const long bbase = ((long)(hglob * 128 + (j0c >> 4) + ks) * 5) * 32 + lane;
#pragma unroll
            for (int nf = 0; nf < 5; nf++) bh[ks][nf] = g_bfragHI[bbase + nf * 32];
        }
        if (c + 1 < 16) {
            const int j0n = j0c + 32;
            if (tid < 128) {
                adjw[buf ^ 1][tid] = g_adjbits[(i0 + tid) * (N_NODES / 32) + (j0n >> 5)];
                u1s[buf ^ 1][tid] = g_u1h[(hg * 4 + (tid >> 5)) * N_NODES + j0n + (tid & 31)];
            } else {
                int q = tid - 128;
                u2s[buf ^ 1][q] = g_u2h[(hg * 4 + (q >> 5)) * N_NODES + j0n + (q & 31)];
            }
        }

#pragma unroll
        for (int kstep = 0; kstep < 2; kstep++) {
            const int jb = kstep * 16 + kq;
            __half2 u1a = *(const __half2*)&u1s[buf][hloc * 32 + jb];
            __half2 u1b = *(const __half2*)&u1s[buf][hloc * 32 + jb + 8];
            __half2 u2a = *(const __half2*)&u2s[buf][hloc * 32 + jb];
            __half2 u2b = *(const __half2*)&u2s[buf][hloc * 32 + jb + 8];
            __half2 uda = __hsub2(u1a, u2a);
            __half2 udb = __hsub2(u1b, u2b);

#pragma unroll
            for (int mf = 0; mf < 4; mf++) {
                uint32_t aw0 = adjw[buf][ihalf + mf * 16 + rq];
                uint32_t aw1 = adjw[buf][ihalf + mf * 16 + rq + 8];
                uint32_t areg[4];
#pragma unroll
                for (int rs = 0; rs < 2; rs++) {
                    uint32_t aw = rs ? aw1 : aw0;
                    __half2 th = th2[mf][rs], e2r = e2b[mf][rs], edr = ed[mf][rs];
                    uint32_t ba = (aw >> jb) & 3u;
                    uint32_t ma = ((ba & 1u) * 0x3C00u) | ((ba >> 1) * 0x3C000000u);
                    __half2 m  = __hge2(u1a, th);
                    __half2 t  = __hfma2(m, uda, u2a);
                    __half2 e  = __hfma2(m, edr, e2r);
                    __half2 w  = __hmul2(__hmul2(t, e), u2h2(ma));
                    areg[rs] = h2u(w);
                    uint32_t bb = (aw >> (jb + 8)) & 3u;
                    uint32_t mb = ((bb & 1u) * 0x3C00u) | ((bb >> 1) * 0x3C000000u);
                    __half2 m2 = __hge2(u1b, th);
                    __half2 t2 = __hfma2(m2, udb, u2b);
                    __half2 e2x = __hfma2(m2, edr, e2r);
                    __half2 w2 = __hmul2(__hmul2(t2, e2x), u2h2(mb));
                    areg[rs + 2] = h2u(w2);
                }
#pragma unroll
                for (int nf = 0; nf < 5; nf++) mma16816(acc[mf][nf], areg, bh[kstep][nf]);
            }
        }
        __syncthreads();
    }

#pragma unroll
    for (int mf = 0; mf < 4; mf++) {
        int r0 = i0 + ihalf + mf * 16 + rq;
        int r1 = r0 + 8;
#pragma unroll
        for (int nf = 0; nf < 4; nf++) {
            int f = nf * 8 + kq;
            *(float2*)&g_pnum[sp][r0 * GDIM + hglob * NF + f] =
                make_float2(acc[mf][nf][0], acc[mf][nf][1]);
            *(float2*)&g_pnum[sp][r1 * GDIM + hglob * NF + f] =
                make_float2(acc[mf][nf][2], acc[mf][nf][3]);
        }
        if ((lane & 3) == 0) {
            g_pz[sp][r0 * NH + hglob] = acc[mf][4][0];
            g_pz[sp][r1 * NH + hglob] = acc[mf][4][2];
        }
    }
}

// ---------------- K4: combine + normalize (4 floats/thread, 512 CTAs, MLP=8) ----------------
__global__ __launch_bounds__(256) void norm_kernel(float* __restrict__ out) {
    const int a4 = (blockIdx.x * 256 + threadIdx.x) * 4;
    const int ih = a4 >> 5;
    float4 v0 = *(const float4*)&g_pnum[0][a4];
    float4 v1 = *(const float4*)&g_pnum[1][a4];
    float4 v2 = *(const float4*)&g_pnum[2][a4];
    float4 v3 = *(const float4*)&g_pnum[3][a4];
    float z = (g_pz[0][ih] + g_pz[1][ih]) + (g_pz[2][ih] + g_pz[3][ih]);
    float inv = 1.0f / z;
    float4 r;
    r.x = ((v0.x + v1.x) + (v2.x + v3.x)) * inv;
    r.y = ((v0.y + v1.y) + (v2.y + v3.y)) * inv;
    r.z = ((v0.z + v1.z) + (v2.z + v3.z)) * inv;
    r.w = ((v0.w + v1.w) + (v2.w + v3.w)) * inv;
    *(float4*)&out[a4] = r;
}

extern "C" void kernel_launch(void* const* d_in, const int* in_sizes, int n_in,
                              void* d_out, int out_size) {
    const float* h_ptr = nullptr;
    const int*   adj   = nullptr;
    const float* W_ptr = nullptr;
    const float* a_ptr = nullptr;
    for (int i = 0; i < n_in; i++) {
        long sz = in_sizes[i];
        if (sz == (long)N_NODES * IN_F)          h_ptr = (const float*)d_in[i];
        else if (sz == (long)N_NODES * N_NODES)  adj   = (const int*)d_in[i];
        else if (sz == (long)IN_F * GDIM)        W_ptr = (const float*)d_in[i];
        else if (sz == 2 * NF)                   a_ptr = (const float*)d_in[i];
    }
    float* out = (float*)d_out;

    prep_kernel<<<1280, 256>>>(h_ptr, W_ptr);
    hgemm_fused<<<dim3(GDIM / 64, N_NODES / 64), 256>>>(a_ptr, adj);
    attn_kernel<<<dim3(N_NODES / 128, 2, NSPLIT), 256>>>();
    norm_kernel<<<(N_NODES * GDIM) / 1024, 256>>>(out);
}